// round 15
// baseline (speedup 1.0000x reference)
#include <cuda_runtime.h>
#include <cuda.h>
#include <cuda_bf16.h>
#include <cstdint>

// Problem constants
#define BATCH 16
#define HGRID 64
#define WGRID 64
#define DIM   512
#define NTOK  (1 + HGRID * WGRID)     // 4097

// Tiling: 32 rows x 16 cols spatial tile, 32 channels (16 ull lanes)
#define CT        32
#define LANES     16
#define TILE_H    32
#define TILE_W    16
#define TINH      (TILE_H + 6)        // 38
#define TINH_A    22                  // chunk 0 rows (covers output rows 0..15)
#define TINH_B    16                  // chunk 1 rows (tile rows 22..37)
#define TINW      (TILE_W + 6)        // 22
#define SPOS      (TINH * TINW)       // 836
#define WP        58                  // weight lane stride: 58*8 mod 128 = 80 -> conflict-free
#define NSLOT     56                  // 7 kr rows x 8 padded kc slots
#define THREADS   256

#define S_IN_ULL   (SPOS * LANES)                 // 13376 (lane-minor [pos][16])
#define S_W_OFF    S_IN_ULL                       // weights after input
#define S_MBAR_OFF (S_IN_ULL + LANES * WP)        // 14304 (2 mbarriers)
#define SMEM_ULL   (S_MBAR_OFF + 4)               // 14308
#define SMEM_BYTES (SMEM_ULL * 8)                 // 114464 (x2 blocks fits)

#define CHUNKA_BYTES (TINH_A * TINW * LANES * 8)  // 61952
#define CHUNKB_BYTES (TINH_B * TINW * LANES * 8)  // 45056

typedef unsigned long long ull;

// One-time fused weights [slot][cl] (slot = kr*8+kc, cl = channel-pair) + bias
__device__ __align__(16) ull g_wf[NSLOT * (DIM / 2)];
__device__ __align__(16) ull g_bs[DIM / 2];

__device__ __forceinline__ ull fma2(ull a, ull b, ull c) {
    ull d;
    asm("fma.rn.f32x2 %0, %1, %2, %3;" : "=l"(d) : "l"(a), "l"(b), "l"(c));
    return d;
}

__device__ __forceinline__ ull pack2(float lo, float hi) {
    ull d;
    asm("mov.b64 %0, {%1, %2};" : "=l"(d) : "f"(lo), "f"(hi));
    return d;
}

__device__ __forceinline__ void cp_async8(uint32_t dst_smem, const void* src) {
    asm volatile("cp.async.ca.shared.global [%0], [%1], 8;"
                 :: "r"(dst_smem), "l"(src));
}

__device__ __forceinline__ void mbar_wait(uint32_t mbar) {
    uint32_t done;
    asm volatile(
        "{\n\t.reg .pred p;\n\t"
        "mbarrier.try_wait.parity.acquire.cta.shared::cta.b64 p, [%1], 0;\n\t"
        "selp.b32 %0, 1, 0, p;\n\t}"
        : "=r"(done) : "r"(mbar) : "memory");
    while (!done) {
        asm volatile(
            "{\n\t.reg .pred p;\n\t"
            "mbarrier.try_wait.parity.acquire.cta.shared::cta.b64 p, [%1], 0, 0x989680;\n\t"
            "selp.b32 %0, 1, 0, p;\n\t}"
            : "=r"(done) : "r"(mbar) : "memory");
    }
}

// ---------------------------------------------------------------------------
// Prep: one thread per channel-pair, contiguous reads of its w7/w5/w3 rows.
// Writes fused weights (padded slot layout) + packed bias.
// ---------------------------------------------------------------------------
__global__ void prep_kernel(const float* __restrict__ w7, const float* __restrict__ b7,
                            const float* __restrict__ w5, const float* __restrict__ b5,
                            const float* __restrict__ w3, const float* __restrict__ b3) {
    const int cl = threadIdx.x;                    // 0..255
    const int c  = 2 * cl;

    float a7[98], a5[50], a3[18];
    #pragma unroll 1
    for (int i = 0; i < 98; ++i) a7[i] = w7[c * 49 + i];
    #pragma unroll 1
    for (int i = 0; i < 50; ++i) a5[i] = w5[c * 25 + i];
    #pragma unroll 1
    for (int i = 0; i < 18; ++i) a3[i] = w3[c * 9 + i];

    #pragma unroll 1
    for (int slot = 0; slot < NSLOT; ++slot) {
        const int kr = slot >> 3, kc = slot & 7;
        ull v = 0ull;
        if (kc < 7) {
            const int k = kr * 7 + kc;
            float v0 = a7[k], v1 = a7[49 + k];
            if (kr >= 1 && kr <= 5 && kc >= 1 && kc <= 5) {
                const int k5 = (kr - 1) * 5 + (kc - 1);
                v0 += a5[k5]; v1 += a5[25 + k5];
            }
            if (kr >= 2 && kr <= 4 && kc >= 2 && kc <= 4) {
                const int k3 = (kr - 2) * 3 + (kc - 2);
                v0 += a3[k3]; v1 += a3[9 + k3];
            }
            if (kr == 3 && kc == 3) { v0 += 1.0f; v1 += 1.0f; }
            v = pack2(v0, v1);
        }
        g_wf[slot * (DIM / 2) + cl] = v;
    }
    g_bs[cl] = pack2(b7[c] + b5[c] + b3[c],
                     b7[c + 1] + b5[c + 1] + b3[c + 1]);
}

// ---------------------------------------------------------------------------
// Conv: split TMA (2 chunks, 2 mbarriers) -> first-half warps start computing
// while chunk 1 streams in. Prefused weights via cp.async; f32x2 math.
// Each thread: 2 rows x 16 cols x 2 channels.
// grid: (16 channel groups, 2x4 spatial tiles, 16 batch), 256 threads.
// ---------------------------------------------------------------------------
__global__ void __launch_bounds__(THREADS, 2)
conv_kernel(const __grid_constant__ CUtensorMap tmapA,
            const __grid_constant__ CUtensorMap tmapB,
            const float* __restrict__ x, float* __restrict__ out) {
    extern __shared__ ull sm[];
    ull* s_in = sm;                    // [SPOS][LANES]  lane-minor
    ull* s_w  = sm + S_W_OFF;          // [LANES][WP]

    const int tid  = threadIdx.x;
    const int lane = tid & (LANES - 1);

    const int c0 = blockIdx.x * CT;
    const int h0 = (blockIdx.y >> 2) * TILE_H;
    const int w0 = (blockIdx.y & 3) * TILE_W;
    const int b  = blockIdx.z;

    ull* o64 = (ull*)out;
    const int cl      = (c0 >> 1) + lane;
    const int tokbase = b * NTOK + 1;              // skip cls token

    const uint32_t smem_base = (uint32_t)__cvta_generic_to_shared(sm);
    const uint32_t mbar0 = smem_base + S_MBAR_OFF * 8;
    const uint32_t mbar1 = mbar0 + 8;

    // --- 1) tid 0: init mbarriers, fence, issue BOTH TMA chunks immediately ---
    if (tid == 0) {
        asm volatile("mbarrier.init.shared.b64 [%0], 1;" :: "r"(mbar0) : "memory");
        asm volatile("mbarrier.init.shared.b64 [%0], 1;" :: "r"(mbar1) : "memory");
        asm volatile("fence.proxy.async.shared::cta;" ::: "memory");
        asm volatile("mbarrier.arrive.expect_tx.shared.b64 _, [%0], %1;"
                     :: "r"(mbar0), "r"((uint32_t)CHUNKA_BYTES) : "memory");
        asm volatile(
            "cp.async.bulk.tensor.4d.shared::cta.global.tile.mbarrier::complete_tx::bytes "
            "[%0], [%1, {%2, %3, %4, %5}], [%6];"
            :: "r"(smem_base), "l"(&tmapA),
               "r"(c0), "r"(w0 - 3), "r"(h0 - 3), "r"(b), "r"(mbar0)
            : "memory");
        asm volatile("mbarrier.arrive.expect_tx.shared.b64 _, [%0], %1;"
                     :: "r"(mbar1), "r"((uint32_t)CHUNKB_BYTES) : "memory");
        asm volatile(
            "cp.async.bulk.tensor.4d.shared::cta.global.tile.mbarrier::complete_tx::bytes "
            "[%0], [%1, {%2, %3, %4, %5}], [%6];"
            :: "r"(smem_base + (uint32_t)(TINH_A * TINW * LANES * 8)), "l"(&tmapB),
               "r"(c0), "r"(w0 - 3), "r"(h0 - 3 + TINH_A), "r"(b), "r"(mbar1)
            : "memory");
    }

    // --- 2) Prefused-weight cp.asyncs (coalesced from g_wf) ---
    {
        const int clb = c0 >> 1;
        const uint32_t swb = smem_base + S_W_OFF * 8;
        #pragma unroll
        for (int i = 0; i < 4; ++i) {
            const int s = tid + i * THREADS;       // need < 896
            if (s < NSLOT * LANES) {
                const int slot = s >> 4;
                const int sl   = s & (LANES - 1);
                cp_async8(swb + (uint32_t)(sl * WP + slot) * 8u,
                          g_wf + slot * (DIM / 2) + clb + sl);
            }
        }
        asm volatile("cp.async.commit_group;" ::: "memory");
    }

    // --- 3) cls token pass-through + bias (under flight) ---
    if (blockIdx.y == 0 && tid < LANES) {
        const size_t off = (size_t)(b * NTOK) * (DIM / 2) + (c0 >> 1) + tid;
        o64[off] = ((const ull*)x)[off];
    }
    const ull bv = g_bs[cl];

    // --- 4) Drain weight cp.asyncs; barrier (weights + mbar-init visible) ---
    asm volatile("cp.async.wait_group 0;" ::: "memory");
    __syncthreads();

    // --- Each thread: 2 rows x 16 cols, 2 channels ---
    const int y   = tid >> 4;           // 0..15 = row pair
    const int or0 = 2 * y;

    // First-half warps (output rows 0..15, tile rows 0..21) need chunk A only.
    mbar_wait(mbar0);
    if (y >= 8) mbar_wait(mbar1);

    const ull* inb = s_in + lane;       // element (r, c) at inb[(r*TINW+c)*16]
    const ull* wb  = s_w + lane * WP;

    ull a0[16], a1[16];
    #pragma unroll
    for (int c = 0; c < 16; ++c) { a0[c] = bv; a1[c] = bv; }

    ull wbuf[8];                        // single weight-row buffer

    #pragma unroll
    for (int ir = 0; ir < 8; ++ir) {    // input rows or0 .. or0+7
        const ull* rowp = inb + (or0 + ir) * (TINW * LANES);
        ull in[22];
        #pragma unroll
        for (int j = 0; j < 22; ++j)
            in[j] = rowp[j * LANES];

        // a1 consumes wbuf (= weight row ir-1) before it is overwritten
        if (ir >= 1) {
            #pragma unroll
            for (int kc = 0; kc < 7; ++kc)
                #pragma unroll
                for (int c = 0; c < 16; ++c)
                    a1[c] = fma2(in[c + kc], wbuf[kc], a1[c]);
        }
        // reload wbuf with weight row ir, then feed a0
        if (ir <= 6) {
            const ulonglong2* wp2 = (const ulonglong2*)(wb + ir * 8);
            #pragma unroll
            for (int j = 0; j < 4; ++j) {
                ulonglong2 v = wp2[j];
                wbuf[2 * j]     = v.x;
                wbuf[2 * j + 1] = v.y;
            }
            #pragma unroll
            for (int kc = 0; kc < 7; ++kc)
                #pragma unroll
                for (int c = 0; c < 16; ++c)
                    a0[c] = fma2(in[c + kc], wbuf[kc], a0[c]);
        }
    }

    // --- Store 2 rows x 16 cols ---
    const int row0 = (tokbase + (h0 + or0) * WGRID + w0) * (DIM / 2) + cl;
    const int row1 = row0 + WGRID * (DIM / 2);
    #pragma unroll
    for (int c = 0; c < 16; ++c) {
        o64[row0 + c * (DIM / 2)] = a0[c];
        o64[row1 + c * (DIM / 2)] = a1[c];
    }
}

// ---------------------------------------------------------------------------
extern "C" void kernel_launch(void* const* d_in, const int* in_sizes, int n_in,
                              void* d_out, int out_size) {
    const float* x  = (const float*)d_in[0];
    const float* w7 = (const float*)d_in[1];
    const float* b7 = (const float*)d_in[2];
    const float* w5 = (const float*)d_in[3];
    const float* b5 = (const float*)d_in[4];
    const float* w3 = (const float*)d_in[5];
    const float* b3 = (const float*)d_in[6];
    float* out = (float*)d_out;

    typedef CUresult (*EncodeFn)(
        CUtensorMap*, CUtensorMapDataType, cuuint32_t, void*,
        const cuuint64_t*, const cuuint64_t*, const cuuint32_t*,
        const cuuint32_t*, CUtensorMapInterleave, CUtensorMapSwizzle,
        CUtensorMapL2promotion, CUtensorMapFloatOOBfill);
    static EncodeFn encode_fn = nullptr;
    if (!encode_fn) {
        cudaDriverEntryPointQueryResult st;
        void* fp = nullptr;
        cudaGetDriverEntryPoint("cuTensorMapEncodeTiled", &fp,
                                cudaEnableDefault, &st);
        encode_fn = (EncodeFn)fp;
    }
    CUtensorMap tmapA, tmapB;
    {
        cuuint64_t dims[4]    = {DIM, WGRID, HGRID, BATCH};
        cuuint64_t strides[3] = {
            (cuuint64_t)DIM * 4,
            (cuuint64_t)WGRID * DIM * 4,
            (cuuint64_t)NTOK * DIM * 4
        };
        cuuint32_t es[4] = {1, 1, 1, 1};
        cuuint32_t boxA[4] = {CT, TINW, TINH_A, 1};    // 32ch x 22 x 22
        encode_fn(&tmapA, CU_TENSOR_MAP_DATA_TYPE_FLOAT32, 4,
                  (void*)(x + DIM), dims, strides, boxA, es,
                  CU_TENSOR_MAP_INTERLEAVE_NONE, CU_TENSOR_MAP_SWIZZLE_NONE,
                  CU_TENSOR_MAP_L2_PROMOTION_L2_128B,
                  CU_TENSOR_MAP_FLOAT_OOB_FILL_NONE);
        cuuint32_t boxB[4] = {CT, TINW, TINH_B, 1};    // 32ch x 22 x 16
        encode_fn(&tmapB, CU_TENSOR_MAP_DATA_TYPE_FLOAT32, 4,
                  (void*)(x + DIM), dims, strides, boxB, es,
                  CU_TENSOR_MAP_INTERLEAVE_NONE, CU_TENSOR_MAP_SWIZZLE_NONE,
                  CU_TENSOR_MAP_L2_PROMOTION_L2_128B,
                  CU_TENSOR_MAP_FLOAT_OOB_FILL_NONE);
    }

    cudaFuncSetAttribute(conv_kernel,
                         cudaFuncAttributeMaxDynamicSharedMemorySize, SMEM_BYTES);

    prep_kernel<<<1, 256>>>(w7, b7, w5, b5, w3, b3);

    dim3 grid(DIM / CT, (HGRID / TILE_H) * (WGRID / TILE_W), BATCH);  // 16,8,16
    conv_kernel<<<grid, THREADS, SMEM_BYTES>>>(tmapA, tmapB, x, out);
}

// round 16
// speedup vs baseline: 1.3869x; 1.3869x over previous
#include <cuda_runtime.h>
#include <cuda.h>
#include <cuda_bf16.h>
#include <cstdint>

// Problem constants
#define BATCH 16
#define HGRID 64
#define WGRID 64
#define DIM   512
#define NTOK  (1 + HGRID * WGRID)     // 4097

// Tiling: 32 rows x 16 cols spatial tile, 32 channels (16 ull lanes)
#define CT        32
#define LANES     16
#define TILE_H    32
#define TILE_W    16
#define TINH      (TILE_H + 6)        // 38
#define TINW      (TILE_W + 6)        // 22
#define SPOS      (TINH * TINW)       // 836
#define WP        58                  // weight lane stride: 58*8 mod 128 = 80 -> conflict-free
#define NSLOT     56                  // 7 kr rows x 8 padded kc slots
#define THREADS   256

#define S_IN_ULL   (SPOS * LANES)                 // 13376 (lane-minor [pos][16])
#define S_W_OFF    S_IN_ULL                       // weights after input
#define S_MBAR_OFF (S_IN_ULL + LANES * WP)        // 14304
#define SMEM_ULL   (S_MBAR_OFF + 4)               // 14308
#define SMEM_BYTES (SMEM_ULL * 8)                 // 114464 (x2 blocks fits)

#define TILE_BYTES (SPOS * LANES * 8)             // 107008

typedef unsigned long long ull;

__device__ __forceinline__ ull fma2(ull a, ull b, ull c) {
    ull d;
    asm("fma.rn.f32x2 %0, %1, %2, %3;" : "=l"(d) : "l"(a), "l"(b), "l"(c));
    return d;
}

__device__ __forceinline__ ull pack2(float lo, float hi) {
    ull d;
    asm("mov.b64 %0, {%1, %2};" : "=l"(d) : "f"(lo), "f"(hi));
    return d;
}

// ---------------------------------------------------------------------------
// Single kernel: TMA input tile + in-block weight fusion (under TMA flight)
// + cls copy + 7x7 depthwise conv in packed f32x2.
// Each thread: 2 rows x 16 cols x 2 channels.
// grid: (16 channel groups, 2x4 spatial tiles, 16 batch), 256 threads.
// ---------------------------------------------------------------------------
__global__ void __launch_bounds__(THREADS, 2)
conv_kernel(const __grid_constant__ CUtensorMap tmap,
            const float* __restrict__ x,
            const float* __restrict__ w7, const float* __restrict__ b7,
            const float* __restrict__ w5, const float* __restrict__ b5,
            const float* __restrict__ w3, const float* __restrict__ b3,
            float* __restrict__ out) {
    extern __shared__ ull sm[];
    ull* s_in = sm;                    // [SPOS][LANES]  lane-minor
    ull* s_w  = sm + S_W_OFF;          // [LANES][WP]

    const int tid  = threadIdx.x;
    const int lane = tid & (LANES - 1);

    const int c0 = blockIdx.x * CT;
    const int h0 = (blockIdx.y >> 2) * TILE_H;
    const int w0 = (blockIdx.y & 3) * TILE_W;
    const int b  = blockIdx.z;

    ull* o64 = (ull*)out;
    const int cl      = (c0 >> 1) + lane;
    const int tokbase = b * NTOK + 1;              // skip cls token

    const uint32_t smem_base = (uint32_t)__cvta_generic_to_shared(sm);
    const uint32_t mbar      = smem_base + S_MBAR_OFF * 8;

    // --- 1) tid 0: mbarrier init, async fence, issue the single TMA load ---
    if (tid == 0) {
        asm volatile("mbarrier.init.shared.b64 [%0], 1;" :: "r"(mbar) : "memory");
        asm volatile("fence.proxy.async.shared::cta;" ::: "memory");
        asm volatile("mbarrier.arrive.expect_tx.shared.b64 _, [%0], %1;"
                     :: "r"(mbar), "r"((uint32_t)TILE_BYTES) : "memory");
        asm volatile(
            "cp.async.bulk.tensor.4d.shared::cta.global.tile.mbarrier::complete_tx::bytes "
            "[%0], [%1, {%2, %3, %4, %5}], [%6];"
            :: "r"(smem_base), "l"(&tmap),
               "r"(c0), "r"(w0 - 3), "r"(h0 - 3), "r"(b), "r"(mbar)
            : "memory");
    }

    // --- 2) In-block weight fusion under TMA flight:
    //        w7 + pad(w5) + pad(w3) + identity -> s_w (padded slot layout) ---
    #pragma unroll 1
    for (int s = tid; s < NSLOT * LANES; s += THREADS) {
        const int slot = s >> 4;                   // 0..55
        const int sl   = s & (LANES - 1);
        const int kr = slot >> 3, kc = slot & 7;
        ull v = 0ull;
        if (kc < 7) {                              // kc==7 is padding
            const int c = c0 + 2 * sl;
            const int k = kr * 7 + kc;
            float v0 = w7[c * 49 + k];
            float v1 = w7[(c + 1) * 49 + k];
            if (kr >= 1 && kr <= 5 && kc >= 1 && kc <= 5) {
                const int k5 = (kr - 1) * 5 + (kc - 1);
                v0 += w5[c * 25 + k5];
                v1 += w5[(c + 1) * 25 + k5];
            }
            if (kr >= 2 && kr <= 4 && kc >= 2 && kc <= 4) {
                const int k3 = (kr - 2) * 3 + (kc - 2);
                v0 += w3[c * 9 + k3];
                v1 += w3[(c + 1) * 9 + k3];
            }
            if (kr == 3 && kc == 3) { v0 += 1.0f; v1 += 1.0f; }
            v = pack2(v0, v1);
        }
        s_w[sl * WP + slot] = v;
    }

    // --- 3) cls token pass-through + bias (still under TMA flight) ---
    if (blockIdx.y == 0 && tid < LANES) {
        const size_t off = (size_t)(b * NTOK) * (DIM / 2) + (c0 >> 1) + tid;
        o64[off] = ((const ull*)x)[off];
    }
    const int cb = c0 + 2 * lane;
    const ull bv = pack2(b7[cb] + b5[cb] + b3[cb],
                         b7[cb + 1] + b5[cb + 1] + b3[cb + 1]);

    // --- 4) Barrier: s_w + mbarrier init visible to all threads ---
    __syncthreads();

    // --- 5) Wait for TMA tile ---
    {
        uint32_t done;
        asm volatile(
            "{\n\t.reg .pred p;\n\t"
            "mbarrier.try_wait.parity.acquire.cta.shared::cta.b64 p, [%1], 0;\n\t"
            "selp.b32 %0, 1, 0, p;\n\t}"
            : "=r"(done) : "r"(mbar) : "memory");
        while (!done) {
            asm volatile(
                "{\n\t.reg .pred p;\n\t"
                "mbarrier.try_wait.parity.acquire.cta.shared::cta.b64 p, [%1], 0, 0x989680;\n\t"
                "selp.b32 %0, 1, 0, p;\n\t}"
                : "=r"(done) : "r"(mbar) : "memory");
        }
    }

    // --- Each thread: 2 rows x 16 cols, 2 channels (packed f32x2 math) ---
    const int y   = tid >> 4;           // 0..15 = row pair
    const int or0 = 2 * y;

    const ull* inb = s_in + lane;       // element (r, c) at inb[(r*TINW+c)*16]
    const ull* wb  = s_w + lane * WP;

    ull a0[16], a1[16];
    #pragma unroll
    for (int c = 0; c < 16; ++c) { a0[c] = bv; a1[c] = bv; }

    ull wbuf[8];                        // single weight-row buffer

    #pragma unroll
    for (int ir = 0; ir < 8; ++ir) {    // input rows or0 .. or0+7
        const ull* rowp = inb + (or0 + ir) * (TINW * LANES);
        ull in[22];
        #pragma unroll
        for (int j = 0; j < 22; ++j)
            in[j] = rowp[j * LANES];

        // a1 consumes wbuf (= weight row ir-1) before it is overwritten
        if (ir >= 1) {
            #pragma unroll
            for (int kc = 0; kc < 7; ++kc)
                #pragma unroll
                for (int c = 0; c < 16; ++c)
                    a1[c] = fma2(in[c + kc], wbuf[kc], a1[c]);
        }
        // reload wbuf with weight row ir, then feed a0
        if (ir <= 6) {
            const ulonglong2* wp2 = (const ulonglong2*)(wb + ir * 8);
            #pragma unroll
            for (int j = 0; j < 4; ++j) {
                ulonglong2 v = wp2[j];
                wbuf[2 * j]     = v.x;
                wbuf[2 * j + 1] = v.y;
            }
            #pragma unroll
            for (int kc = 0; kc < 7; ++kc)
                #pragma unroll
                for (int c = 0; c < 16; ++c)
                    a0[c] = fma2(in[c + kc], wbuf[kc], a0[c]);
        }
    }

    // --- Store 2 rows x 16 cols ---
    const int row0 = (tokbase + (h0 + or0) * WGRID + w0) * (DIM / 2) + cl;
    const int row1 = row0 + WGRID * (DIM / 2);
    #pragma unroll
    for (int c = 0; c < 16; ++c) {
        o64[row0 + c * (DIM / 2)] = a0[c];
        o64[row1 + c * (DIM / 2)] = a1[c];
    }
}

// ---------------------------------------------------------------------------
extern "C" void kernel_launch(void* const* d_in, const int* in_sizes, int n_in,
                              void* d_out, int out_size) {
    const float* x  = (const float*)d_in[0];
    const float* w7 = (const float*)d_in[1];
    const float* b7 = (const float*)d_in[2];
    const float* w5 = (const float*)d_in[3];
    const float* b5 = (const float*)d_in[4];
    const float* w3 = (const float*)d_in[5];
    const float* b3 = (const float*)d_in[6];
    float* out = (float*)d_out;

    typedef CUresult (*EncodeFn)(
        CUtensorMap*, CUtensorMapDataType, cuuint32_t, void*,
        const cuuint64_t*, const cuuint64_t*, const cuuint32_t*,
        const cuuint32_t*, CUtensorMapInterleave, CUtensorMapSwizzle,
        CUtensorMapL2promotion, CUtensorMapFloatOOBfill);
    static EncodeFn encode_fn = nullptr;
    if (!encode_fn) {
        cudaDriverEntryPointQueryResult st;
        void* fp = nullptr;
        cudaGetDriverEntryPoint("cuTensorMapEncodeTiled", &fp,
                                cudaEnableDefault, &st);
        encode_fn = (EncodeFn)fp;
    }
    CUtensorMap tmap;
    {
        // 4D tensor over x (fp32): dim0=channels, dim1=w, dim2=h, dim3=batch.
        // Base skips batch-0 cls token; batch stride absorbs per-batch cls.
        cuuint64_t dims[4]    = {DIM, WGRID, HGRID, BATCH};
        cuuint64_t strides[3] = {
            (cuuint64_t)DIM * 4,
            (cuuint64_t)WGRID * DIM * 4,
            (cuuint64_t)NTOK * DIM * 4
        };
        cuuint32_t box[4] = {CT, TINW, TINH, 1};       // 32 ch x 22 x 38
        cuuint32_t es[4]  = {1, 1, 1, 1};
        encode_fn(&tmap, CU_TENSOR_MAP_DATA_TYPE_FLOAT32, 4,
                  (void*)(x + DIM), dims, strides, box, es,
                  CU_TENSOR_MAP_INTERLEAVE_NONE, CU_TENSOR_MAP_SWIZZLE_NONE,
                  CU_TENSOR_MAP_L2_PROMOTION_L2_128B,
                  CU_TENSOR_MAP_FLOAT_OOB_FILL_NONE);
    }

    cudaFuncSetAttribute(conv_kernel,
                         cudaFuncAttributeMaxDynamicSharedMemorySize, SMEM_BYTES);

    dim3 grid(DIM / CT, (HGRID / TILE_H) * (WGRID / TILE_W), BATCH);  // 16,8,16
    conv_kernel<<<grid, THREADS, SMEM_BYTES>>>(tmap, x, w7, b7, w5, b5, w3, b3, out);
}

// round 17
// speedup vs baseline: 1.5598x; 1.1247x over previous
#include <cuda_runtime.h>
#include <cuda.h>
#include <cuda_bf16.h>
#include <cstdint>

// Problem constants
#define BATCH 16
#define HGRID 64
#define WGRID 64
#define DIM   512
#define NTOK  (1 + HGRID * WGRID)     // 4097

// Tiling: 32 rows x 16 cols spatial tile, 32 channels (16 ull lanes)
#define CT        32
#define LANES     16
#define TILE_H    32
#define TILE_W    16
#define TINH      (TILE_H + 6)        // 38
#define TINW      (TILE_W + 6)        // 22
#define SPOS      (TINH * TINW)       // 836
#define WP        58                  // weight lane stride (ull)
#define NSLOT     56                  // 7 kr rows x 8 padded kc slots
#define THREADS   256
#define NTASK     2048                // 16 cg x 8 spatial x 16 batch

#define S_IN_ULL   (SPOS * LANES)                 // 13376 ull per buffer
#define S_W_OFF    (2 * S_IN_ULL)                 // 26752
#define S_MBAR_OFF (S_W_OFF + LANES * WP)         // 27680
#define SMEM_ULL   (S_MBAR_OFF + 2)               // 27682
#define SMEM_BYTES (SMEM_ULL * 8)                 // 221456 (<= 227KB dyn max)

#define TILE_BYTES (SPOS * LANES * 8)             // 107008

typedef unsigned long long ull;

__device__ __forceinline__ ull fma2(ull a, ull b, ull c) {
    ull d;
    asm("fma.rn.f32x2 %0, %1, %2, %3;" : "=l"(d) : "l"(a), "l"(b), "l"(c));
    return d;
}

__device__ __forceinline__ ull pack2(float lo, float hi) {
    ull d;
    asm("mov.b64 %0, {%1, %2};" : "=l"(d) : "f"(lo), "f"(hi));
    return d;
}

__device__ __forceinline__ void mbar_wait(uint32_t mbar, uint32_t phase) {
    uint32_t done;
    asm volatile(
        "{\n\t.reg .pred p;\n\t"
        "mbarrier.try_wait.parity.acquire.cta.shared::cta.b64 p, [%1], %2;\n\t"
        "selp.b32 %0, 1, 0, p;\n\t}"
        : "=r"(done) : "r"(mbar), "r"(phase) : "memory");
    while (!done) {
        asm volatile(
            "{\n\t.reg .pred p;\n\t"
            "mbarrier.try_wait.parity.acquire.cta.shared::cta.b64 p, [%1], %2, 0x989680;\n\t"
            "selp.b32 %0, 1, 0, p;\n\t}"
            : "=r"(done) : "r"(mbar), "r"(phase) : "memory");
    }
}

// ---------------------------------------------------------------------------
// Persistent kernel: one block per SM, ~13-14 (cg, tile, batch) tasks each,
// double-buffered TMA tiles (load task i+1 while computing task i).
// Task encoding: t = cg*128 + sp*16 + b  (cg-major -> <=1 weight refuse/block)
// ---------------------------------------------------------------------------
__global__ void __launch_bounds__(THREADS, 1)
conv_kernel(const __grid_constant__ CUtensorMap tmap,
            const float* __restrict__ x,
            const float* __restrict__ w7, const float* __restrict__ b7,
            const float* __restrict__ w5, const float* __restrict__ b5,
            const float* __restrict__ w3, const float* __restrict__ b3,
            float* __restrict__ out) {
    extern __shared__ ull sm[];
    ull* s_w = sm + S_W_OFF;           // [LANES][WP]

    const int tid  = threadIdx.x;
    const int lane = tid & (LANES - 1);

    ull* o64 = (ull*)out;

    const uint32_t smem_base = (uint32_t)__cvta_generic_to_shared(sm);
    const uint32_t mbar0 = smem_base + S_MBAR_OFF * 8;
    const uint32_t mbar1 = mbar0 + 8;

    // Task range for this block (cg-major contiguous slice)
    const int G  = gridDim.x;
    const int t0 = (int)(((long)blockIdx.x * NTASK) / G);
    const int t1 = (int)(((long)(blockIdx.x + 1) * NTASK) / G);

    // --- Prologue: mbarriers + first TMA ---
    if (tid == 0) {
        asm volatile("mbarrier.init.shared.b64 [%0], 1;" :: "r"(mbar0) : "memory");
        asm volatile("mbarrier.init.shared.b64 [%0], 1;" :: "r"(mbar1) : "memory");
        asm volatile("fence.proxy.async.shared::cta;" ::: "memory");
        const int b  = t0 & 15;
        const int sp = (t0 >> 4) & 7;
        const int cg = t0 >> 7;
        asm volatile("mbarrier.arrive.expect_tx.shared.b64 _, [%0], %1;"
                     :: "r"(mbar0), "r"((uint32_t)TILE_BYTES) : "memory");
        asm volatile(
            "cp.async.bulk.tensor.4d.shared::cta.global.tile.mbarrier::complete_tx::bytes "
            "[%0], [%1, {%2, %3, %4, %5}], [%6];"
            :: "r"(smem_base), "l"(&tmap),
               "r"(cg * CT), "r"((sp & 3) * TILE_W - 3),
               "r"((sp >> 2) * TILE_H - 3), "r"(b), "r"(mbar0)
            : "memory");
    }

    // --- cls token pass-through (blocks 0..15, under TMA flight) ---
    if (blockIdx.x < BATCH) {
        const size_t off = (size_t)blockIdx.x * NTOK * (DIM / 2) + tid;
        o64[off] = ((const ull*)x)[off];
    }

    // --- Weight fusion for first cg (under TMA flight) ---
    int cg_cur = t0 >> 7;
    #pragma unroll 1
    for (int s = tid; s < NSLOT * LANES; s += THREADS) {
        const int slot = s >> 4;
        const int sl   = s & (LANES - 1);
        const int kr = slot >> 3, kc = slot & 7;
        ull v = 0ull;
        if (kc < 7) {
            const int c = cg_cur * CT + 2 * sl;
            const int k = kr * 7 + kc;
            float v0 = w7[c * 49 + k], v1 = w7[(c + 1) * 49 + k];
            if (kr >= 1 && kr <= 5 && kc >= 1 && kc <= 5) {
                const int k5 = (kr - 1) * 5 + (kc - 1);
                v0 += w5[c * 25 + k5]; v1 += w5[(c + 1) * 25 + k5];
            }
            if (kr >= 2 && kr <= 4 && kc >= 2 && kc <= 4) {
                const int k3 = (kr - 2) * 3 + (kc - 2);
                v0 += w3[c * 9 + k3]; v1 += w3[(c + 1) * 9 + k3];
            }
            if (kr == 3 && kc == 3) { v0 += 1.0f; v1 += 1.0f; }
            v = pack2(v0, v1);
        }
        s_w[sl * WP + slot] = v;
    }
    ull bv = pack2(b7[cg_cur * CT + 2 * lane] + b5[cg_cur * CT + 2 * lane] + b3[cg_cur * CT + 2 * lane],
                   b7[cg_cur * CT + 2 * lane + 1] + b5[cg_cur * CT + 2 * lane + 1] + b3[cg_cur * CT + 2 * lane + 1]);

    __syncthreads();   // mbar init + s_w visible

    const int y   = tid >> 4;           // 0..15 = row pair
    const int or0 = 2 * y;

    int pp0 = 0, pp1 = 0;

    #pragma unroll 1
    for (int t = t0, i = 0; t < t1; ++t, ++i) {
        // 1) Prefetch next task's tile into the free buffer
        if (tid == 0 && t + 1 < t1) {
            const int tn = t + 1;
            const int bn  = tn & 15;
            const int spn = (tn >> 4) & 7;
            const int cgn = tn >> 7;
            const uint32_t mb  = ((i + 1) & 1) ? mbar1 : mbar0;
            const uint32_t dst = smem_base + (uint32_t)(((i + 1) & 1) * S_IN_ULL * 8);
            asm volatile("mbarrier.arrive.expect_tx.shared.b64 _, [%0], %1;"
                         :: "r"(mb), "r"((uint32_t)TILE_BYTES) : "memory");
            asm volatile(
                "cp.async.bulk.tensor.4d.shared::cta.global.tile.mbarrier::complete_tx::bytes "
                "[%0], [%1, {%2, %3, %4, %5}], [%6];"
                :: "r"(dst), "l"(&tmap),
                   "r"(cgn * CT), "r"((spn & 3) * TILE_W - 3),
                   "r"((spn >> 2) * TILE_H - 3), "r"(bn), "r"(mb)
                : "memory");
        }

        // 2) Weight refuse on cg change (block-uniform, <=1 per block)
        const int cg = t >> 7;
        if (cg != cg_cur) {
            cg_cur = cg;
            #pragma unroll 1
            for (int s = tid; s < NSLOT * LANES; s += THREADS) {
                const int slot = s >> 4;
                const int sl   = s & (LANES - 1);
                const int kr = slot >> 3, kc = slot & 7;
                ull v = 0ull;
                if (kc < 7) {
                    const int c = cg * CT + 2 * sl;
                    const int k = kr * 7 + kc;
                    float v0 = w7[c * 49 + k], v1 = w7[(c + 1) * 49 + k];
                    if (kr >= 1 && kr <= 5 && kc >= 1 && kc <= 5) {
                        const int k5 = (kr - 1) * 5 + (kc - 1);
                        v0 += w5[c * 25 + k5]; v1 += w5[(c + 1) * 25 + k5];
                    }
                    if (kr >= 2 && kr <= 4 && kc >= 2 && kc <= 4) {
                        const int k3 = (kr - 2) * 3 + (kc - 2);
                        v0 += w3[c * 9 + k3]; v1 += w3[(c + 1) * 9 + k3];
                    }
                    if (kr == 3 && kc == 3) { v0 += 1.0f; v1 += 1.0f; }
                    v = pack2(v0, v1);
                }
                s_w[sl * WP + slot] = v;
            }
            bv = pack2(b7[cg * CT + 2 * lane] + b5[cg * CT + 2 * lane] + b3[cg * CT + 2 * lane],
                       b7[cg * CT + 2 * lane + 1] + b5[cg * CT + 2 * lane + 1] + b3[cg * CT + 2 * lane + 1]);
            __syncthreads();
        }

        // 3) Wait current tile
        if (i & 1) { mbar_wait(mbar1, pp1); pp1 ^= 1; }
        else       { mbar_wait(mbar0, pp0); pp0 ^= 1; }

        // 4) Compute: 2 rows x 16 cols x 2 channels per thread
        const ull* inb = sm + (size_t)(i & 1) * S_IN_ULL + lane;
        const ull* wb  = s_w + lane * WP;

        ull a0[16], a1[16];
        #pragma unroll
        for (int c = 0; c < 16; ++c) { a0[c] = bv; a1[c] = bv; }

        ull wbuf[8];
        #pragma unroll
        for (int ir = 0; ir < 8; ++ir) {
            const ull* rowp = inb + (or0 + ir) * (TINW * LANES);
            ull in[22];
            #pragma unroll
            for (int j = 0; j < 22; ++j)
                in[j] = rowp[j * LANES];

            if (ir >= 1) {
                #pragma unroll
                for (int kc = 0; kc < 7; ++kc)
                    #pragma unroll
                    for (int c = 0; c < 16; ++c)
                        a1[c] = fma2(in[c + kc], wbuf[kc], a1[c]);
            }
            if (ir <= 6) {
                const ulonglong2* wp2 = (const ulonglong2*)(wb + ir * 8);
                #pragma unroll
                for (int j = 0; j < 4; ++j) {
                    ulonglong2 v = wp2[j];
                    wbuf[2 * j] = v.x; wbuf[2 * j + 1] = v.y;
                }
                #pragma unroll
                for (int kc = 0; kc < 7; ++kc)
                    #pragma unroll
                    for (int c = 0; c < 16; ++c)
                        a0[c] = fma2(in[c + kc], wbuf[kc], a0[c]);
            }
        }

        // 5) Store
        const int b  = t & 15;
        const int sp = (t >> 4) & 7;
        const int h0 = (sp >> 2) * TILE_H;
        const int w0 = (sp & 3) * TILE_W;
        const int cl = (cg << 4) + lane;           // cg*32/2 + lane
        const int row0 = ((b * NTOK + 1) + (h0 + or0) * WGRID + w0) * (DIM / 2) + cl;
        const int row1 = row0 + WGRID * (DIM / 2);
        #pragma unroll
        for (int c = 0; c < 16; ++c) {
            o64[row0 + c * (DIM / 2)] = a0[c];
            o64[row1 + c * (DIM / 2)] = a1[c];
        }

        // 6) Buffer (i&1) fully consumed -> safe for TMA at next iter's top
        __syncthreads();
    }
}

// ---------------------------------------------------------------------------
extern "C" void kernel_launch(void* const* d_in, const int* in_sizes, int n_in,
                              void* d_out, int out_size) {
    const float* x  = (const float*)d_in[0];
    const float* w7 = (const float*)d_in[1];
    const float* b7 = (const float*)d_in[2];
    const float* w5 = (const float*)d_in[3];
    const float* b5 = (const float*)d_in[4];
    const float* w3 = (const float*)d_in[5];
    const float* b3 = (const float*)d_in[6];
    float* out = (float*)d_out;

    typedef CUresult (*EncodeFn)(
        CUtensorMap*, CUtensorMapDataType, cuuint32_t, void*,
        const cuuint64_t*, const cuuint64_t*, const cuuint32_t*,
        const cuuint32_t*, CUtensorMapInterleave, CUtensorMapSwizzle,
        CUtensorMapL2promotion, CUtensorMapFloatOOBfill);
    static EncodeFn encode_fn = nullptr;
    if (!encode_fn) {
        cudaDriverEntryPointQueryResult st;
        void* fp = nullptr;
        cudaGetDriverEntryPoint("cuTensorMapEncodeTiled", &fp,
                                cudaEnableDefault, &st);
        encode_fn = (EncodeFn)fp;
    }
    CUtensorMap tmap;
    {
        cuuint64_t dims[4]    = {DIM, WGRID, HGRID, BATCH};
        cuuint64_t strides[3] = {
            (cuuint64_t)DIM * 4,
            (cuuint64_t)WGRID * DIM * 4,
            (cuuint64_t)NTOK * DIM * 4
        };
        cuuint32_t box[4] = {CT, TINW, TINH, 1};       // 32 ch x 22 x 38
        cuuint32_t es[4]  = {1, 1, 1, 1};
        encode_fn(&tmap, CU_TENSOR_MAP_DATA_TYPE_FLOAT32, 4,
                  (void*)(x + DIM), dims, strides, box, es,
                  CU_TENSOR_MAP_INTERLEAVE_NONE, CU_TENSOR_MAP_SWIZZLE_NONE,
                  CU_TENSOR_MAP_L2_PROMOTION_L2_128B,
                  CU_TENSOR_MAP_FLOAT_OOB_FILL_NONE);
    }

    static int nsm = 0;
    if (!nsm) {
        cudaDeviceGetAttribute(&nsm, cudaDevAttrMultiProcessorCount, 0);
        if (nsm <= 0) nsm = 148;
    }

    cudaFuncSetAttribute(conv_kernel,
                         cudaFuncAttributeMaxDynamicSharedMemorySize, SMEM_BYTES);

    conv_kernel<<<nsm, THREADS, SMEM_BYTES>>>(tmap, x, w7, b7, w5, b5, w3, b3, out);
}